// round 14
// baseline (speedup 1.0000x reference)
#include <cuda_runtime.h>
#include <cuda_fp16.h>
#include <cstdint>

// ============================================================================
// TTConv -> folded dense 256->256 3x3 conv -> Winograd F(2x2,3x3), UNFUSED.
// Round 14: GEMM cp.async pipeline deepened to 4 stages (wait_group 3);
// wino_output doubled to 256 thr/block (2 o per block) for DRAM MLP.
// ============================================================================

// ---------------- device scratch (no allocations allowed) -------------------
__device__ float  g_beff[256];
__device__ __half g_Usw[2 * 16 * 8 * 128 * 32];     // 2 MB
__device__ __half g_V[16ull * 8192 * 256];          // 64 MB
__device__ __half g_M[16ull * 256 * 8192];          // 64 MB

// ---------------- helpers ---------------------------------------------------
__device__ __forceinline__ uint32_t smem_u32(const void* p) {
    uint32_t a;
    asm("{ .reg .u64 t; cvta.to.shared.u64 t, %1; cvt.u32.u64 %0, t; }"
        : "=r"(a) : "l"(p));
    return a;
}

#define CP16(dst, src) \
    asm volatile("cp.async.ca.shared.global [%0], [%1], 16;" \
                 :: "r"(dst), "l"(src) : "memory")
#define CP_COMMIT() asm volatile("cp.async.commit_group;" ::: "memory")
#define CP_WAITN(n) asm volatile("cp.async.wait_group %0;" :: "n"(n) : "memory")

#define LDSM4(r0, r1, r2, r3, addr) \
    asm volatile("ldmatrix.sync.aligned.m8n8.x4.shared.b16 {%0,%1,%2,%3}, [%4];" \
                 : "=r"(r0), "=r"(r1), "=r"(r2), "=r"(r3) : "r"(addr))

#define MMA16816(c, a0, a1, a2, a3, b0, b1) \
    asm volatile("mma.sync.aligned.m16n8k16.row.col.f32.f16.f16.f32 " \
                 "{%0,%1,%2,%3}, {%4,%5,%6,%7}, {%8,%9}, {%0,%1,%2,%3};" \
                 : "+f"((c)[0]), "+f"((c)[1]), "+f"((c)[2]), "+f"((c)[3]) \
                 : "r"(a0), "r"(a1), "r"(a2), "r"(a3), "r"(b0), "r"(b1))

// ---------------------------------------------------------------------------
// K1 (merged): weight transform + beff.   [proven round-13]
// ---------------------------------------------------------------------------
__global__ void wino_weights(const float* __restrict__ core1,
                             const float* __restrict__ core2,
                             const float* __restrict__ core3,
                             const float* __restrict__ conv_w,
                             const float* __restrict__ conv_b) {
    __shared__ float Psl[1024];
    __shared__ float Gsl[4][144];
    __shared__ float bsl[4][16];
    __shared__ float red[256];

    int o = blockIdx.x, ic = threadIdx.x, tid = threadIdx.x;
    int a = o >> 6, c = (o >> 3) & 7, d = o & 7;

#pragma unroll
    for (int it = 0; it < 4; ++it) {
        int e = tid + it * 256;
        int u = e & 15, k = (e >> 4) & 7, j = (e >> 7) & 7;
        float s = 0.f;
#pragma unroll
        for (int v = 0; v < 16; ++v)
            s += core2[(c * 16 + v) * 128 + u * 8 + j] * core3[d * 128 + v * 8 + k];
        Psl[e] = s;
    }
    for (int e = tid; e < 576; e += 256) {
        int i = e / 144, rem = e - i * 144;
        int tap = rem >> 4, u = rem & 15;
        float s = 0.f;
#pragma unroll
        for (int r = 0; r < 16; ++r)
            s += core1[(a * 16 + u) * 64 + r * 4 + i] * conv_w[r * 9 + tap];
        Gsl[i][rem] = s;
    }
    if (tid < 64) {
        int i = tid >> 4, u = tid & 15;
        float s = 0.f;
#pragma unroll
        for (int r = 0; r < 16; ++r)
            s += core1[(a * 16 + u) * 64 + r * 4 + i] * conv_b[r];
        bsl[i][u] = s;
    }
    __syncthreads();

    int i = ic >> 6, j = (ic >> 3) & 7, k = ic & 7;
    float Pu[16];
#pragma unroll
    for (int u = 0; u < 16; ++u) Pu[u] = Psl[(j * 8 + k) * 16 + u];

    float f[3][3];
#pragma unroll
    for (int tap = 0; tap < 9; ++tap) {
        float s = 0.f;
#pragma unroll
        for (int u = 0; u < 16; ++u) s += Gsl[i][tap * 16 + u] * Pu[u];
        f[tap / 3][tap % 3] = s;
    }
    float t[4][3];
#pragma unroll
    for (int cc = 0; cc < 3; ++cc) {
        t[0][cc] = f[0][cc];
        t[1][cc] = 0.5f * (f[0][cc] + f[1][cc] + f[2][cc]);
        t[2][cc] = 0.5f * (f[0][cc] - f[1][cc] + f[2][cc]);
        t[3][cc] = f[2][cc];
    }
    float u4[4][4];
#pragma unroll
    for (int r = 0; r < 4; ++r) {
        u4[r][0] = t[r][0];
        u4[r][1] = 0.5f * (t[r][0] + t[r][1] + t[r][2]);
        u4[r][2] = 0.5f * (t[r][0] - t[r][1] + t[r][2]);
        u4[r][3] = t[r][2];
    }
    int kk = ic & 31, icb = ic >> 5;
    int o_l = o & 127, mh = o >> 7;
    int swkk = ((((kk >> 3) ^ ((o_l >> 1) & 3)) << 3) | (kk & 7));
#pragma unroll
    for (int p = 0; p < 16; ++p)
        g_Usw[((size_t)((mh * 16 + p) * 8 + icb) * 128 + o_l) * 32 + swkk] =
            __float2half_rn(u4[p >> 2][p & 3]);

    float bp = 0.f;
#pragma unroll
    for (int u = 0; u < 16; ++u) bp += bsl[i][u] * Pu[u];
    red[ic] = bp;
    __syncthreads();
    for (int s = 128; s > 0; s >>= 1) {
        if (ic < s) red[ic] += red[ic + s];
        __syncthreads();
    }
    if (ic == 0) g_beff[o] = red[0];
}

// ---------------------------------------------------------------------------
// K2: input transform -> g_V.   [proven]
// ---------------------------------------------------------------------------
__global__ void wino_input(const float* __restrict__ X) {
    int ty = blockIdx.x, icb = blockIdx.y, b = blockIdx.z;
    int tid = threadIdx.x;
    __shared__ float xs[4][66][33];

    {
        const float* Xb = X + ((size_t)b * 256 + icb * 32) * 4096;
#pragma unroll 4
        for (int it = 0; it < 32; ++it) {
            int e = tid + it * 256;
            int rem = e & 255;
            int y = rem >> 6, x = rem & 63;
            int gy = 2 * ty - 1 + y;
            float v = 0.f;
            if (gy >= 0 && gy < 64) v = Xb[((size_t)it * 64 + gy) * 64 + x];
            xs[y][x + 1][it] = v;
        }
        int icl = tid & 31, y = (tid >> 5) & 3, side = tid >> 7;
        xs[y][side ? 65 : 0][icl] = 0.f;
    }
    __syncthreads();

    int w = tid >> 5, lane = tid & 31;
    int n_row = (b * 32 + ty) * 32;
#pragma unroll
    for (int tt = 0; tt < 4; ++tt) {
        int tx = w * 4 + tt;
        int n = n_row + tx;
        float d0[4], d1[4], d2[4], d3[4];
#pragma unroll
        for (int cc = 0; cc < 4; ++cc) {
            d0[cc] = xs[0][2 * tx + cc][lane];
            d1[cc] = xs[1][2 * tx + cc][lane];
            d2[cc] = xs[2][2 * tx + cc][lane];
            d3[cc] = xs[3][2 * tx + cc][lane];
        }
        float w0[4], w1[4], w2[4], w3[4];
#pragma unroll
        for (int cc = 0; cc < 4; ++cc) {
            w0[cc] = d0[cc] - d2[cc];
            w1[cc] = d1[cc] + d2[cc];
            w2[cc] = d2[cc] - d1[cc];
            w3[cc] = d1[cc] - d3[cc];
        }
        float v[4][4];
#pragma unroll
        for (int r = 0; r < 4; ++r) {
            const float* wr = (r == 0) ? w0 : (r == 1) ? w1 : (r == 2) ? w2 : w3;
            v[r][0] = wr[0] - wr[2];
            v[r][1] = wr[1] + wr[2];
            v[r][2] = wr[2] - wr[1];
            v[r][3] = wr[1] - wr[3];
        }
        __half* Vb = g_V + (size_t)n * 256 + icb * 32 + lane;
#pragma unroll
        for (int p = 0; p < 16; ++p)
            Vb[(size_t)p * 8192 * 256] = __float2half_rn(v[p >> 2][p & 3]);
    }
}

// ---------------------------------------------------------------------------
// K3: batched GEMM, 1024-CTA grid, 4-stage cp.async pipeline.
// ---------------------------------------------------------------------------
static constexpr int BA   = 8192;
static constexpr int BB   = 20480;
static constexpr int BSTG = BA + BB;            // 28672
static constexpr int GEMM_SMEM = 4 * BSTG;      // 114688

__global__ __launch_bounds__(256, 1)
void wino_gemm() {
    extern __shared__ char smc[];
    const uint32_t sb = smem_u32(smc);
    const int tid  = threadIdx.x;
    const int warp = tid >> 5, lane = tid & 31;
    const int warpM = warp >> 2;
    const int warpN = warp & 3;
    const int n0 = blockIdx.x * 256;
    const int mh = blockIdx.y;
    const int p  = blockIdx.z;

    const int r15 = lane & 15, hi = lane >> 4;
    const int sw  = (r15 >> 1) & 3;
    const uint32_t l0 = (uint32_t)(r15 * 64 + ((hi ^ sw) << 4));
    const uint32_t l1 = (uint32_t)(r15 * 64 + (((2 + hi) ^ sw) << 4));
    const uint32_t xLane = (uint32_t)((((lane >> 4) & 1) * 8 + (lane & 7)) * 80 +
                                      ((lane >> 3) & 1) * 16);

    auto stage = [&](int kc) {
        const int buf = kc & 3;
        uint32_t dst = sb + buf * BSTG;
        const char* srcA = (const char*)(g_Usw +
            (size_t)((mh * 16 + p) * 8 + kc) * 4096);
        CP16(dst + tid * 16, srcA + tid * 16);
        CP16(dst + (tid + 256) * 16, srcA + (tid + 256) * 16);
        const char* srcB = (const char*)(g_V + ((size_t)p * 8192 + n0) * 256) + kc * 64;
        uint32_t dstB = dst + BA;
#pragma unroll
        for (int i = 0; i < 4; ++i) {
            int e = tid + i * 256;
            int row = e >> 2, cc = e & 3;
            CP16(dstB + row * 80 + cc * 16, srcB + (size_t)row * 512 + cc * 16);
        }
    };

    float acc[4][8][4];
#pragma unroll
    for (int m = 0; m < 4; ++m)
#pragma unroll
        for (int n = 0; n < 8; ++n)
#pragma unroll
            for (int q = 0; q < 4; ++q) acc[m][n][q] = 0.f;

    stage(0); CP_COMMIT();
    stage(1); CP_COMMIT();
    stage(2); CP_COMMIT();
    stage(3); CP_COMMIT();

    for (int kc = 0; kc < 8; ++kc) {
        const int buf = kc & 3;
        switch (kc) {
            case 5:  CP_WAITN(2); break;
            case 6:  CP_WAITN(1); break;
            case 7:  CP_WAITN(0); break;
            default: CP_WAITN(3); break;
        }
        __syncthreads();
        const uint32_t aB = sb + buf * BSTG;
        const uint32_t bB = aB + BA;
        const uint32_t xT = bB + (uint32_t)(warpN * 64 * 80) + xLane;

#pragma unroll
        for (int ks = 0; ks < 2; ++ks) {
            const uint32_t lks = ks ? l1 : l0;
            uint32_t af[4][4];
#pragma unroll
            for (int mt = 0; mt < 4; ++mt)
                LDSM4(af[mt][0], af[mt][1], af[mt][2], af[mt][3],
                      aB + (uint32_t)((warpM * 64 + mt * 16) * 64) + lks);
#pragma unroll
            for (int q = 0; q < 4; ++q) {
                uint32_t b0, b1, b2, b3;
                LDSM4(b0, b1, b2, b3, xT + q * (16 * 80) + ks * 32);
#pragma unroll
                for (int mt = 0; mt < 4; ++mt) {
                    MMA16816(acc[mt][2 * q],     af[mt][0], af[mt][1],
                             af[mt][2], af[mt][3], b0, b1);
                    MMA16816(acc[mt][2 * q + 1], af[mt][0], af[mt][1],
                             af[mt][2], af[mt][3], b2, b3);
                }
            }
        }
        __syncthreads();
        if (kc + 4 < 8) { stage(kc + 4); CP_COMMIT(); }
    }

#pragma unroll
    for (int mt = 0; mt < 4; ++mt) {
        int oA = mh * 128 + warpM * 64 + mt * 16 + (lane >> 2);
        __half* baseLo = g_M + ((size_t)p * 256 + oA) * 8192 + n0 +
                         warpN * 64 + (lane & 3) * 2;
        __half* baseHi = baseLo + (size_t)8 * 8192;
#pragma unroll
        for (int nt = 0; nt < 8; ++nt) {
            __half2 vLo = __floats2half2_rn(acc[mt][nt][0], acc[mt][nt][1]);
            __half2 vHi = __floats2half2_rn(acc[mt][nt][2], acc[mt][nt][3]);
            *reinterpret_cast<__half2*>(baseLo + nt * 8) = vLo;
            *reinterpret_cast<__half2*>(baseHi + nt * 8) = vHi;
        }
    }
}

// ---------------------------------------------------------------------------
// K4: output transform. 256 thr/block, 2 o per block (grid 1024) for 2x MLP.
// ---------------------------------------------------------------------------
__global__ void wino_output(float* __restrict__ out) {
    int blk = blockIdx.x;
    int b = blk >> 7, opair = blk & 127;
    int tid = threadIdx.x;
    int o = opair * 2 + (tid >> 7);
    int tsub = tid & 127;
    int nbase = b * 1024 + tsub * 8;

    uint4 mv[16];
#pragma unroll
    for (int p = 0; p < 16; ++p)
        mv[p] = *reinterpret_cast<const uint4*>(
            g_M + ((size_t)p * 256 + o) * 8192 + nbase);

    float bv = g_beff[o];
    float row0[16], row1[16];
#pragma unroll
    for (int t = 0; t < 8; ++t) {
        float m[16];
#pragma unroll
        for (int p = 0; p < 16; ++p) {
            unsigned wbits = reinterpret_cast<const unsigned*>(&mv[p])[t >> 1];
            __half2 h = *reinterpret_cast<__half2*>(&wbits);
            m[p] = (t & 1) ? __high2float(h) : __low2float(h);
        }
        float z0[4], z1[4];
#pragma unroll
        for (int cc = 0; cc < 4; ++cc) {
            z0[cc] = m[cc] + m[4 + cc] + m[8 + cc];
            z1[cc] = m[4 + cc] - m[8 + cc] - m[12 + cc];
        }
        row0[2 * t]     = z0[0] + z0[1] + z0[2] + bv;
        row0[2 * t + 1] = z0[1] - z0[2] - z0[3] + bv;
        row1[2 * t]     = z1[0] + z1[1] + z1[2] + bv;
        row1[2 * t + 1] = z1[1] - z1[2] - z1[3] + bv;
    }

    int ty = (nbase >> 5) & 31;
    int tx0 = nbase & 31;
    float* po = out + (((size_t)b * 256 + o) * 64 + 2 * ty) * 64 + 2 * tx0;
#pragma unroll
    for (int q = 0; q < 4; ++q) {
        *reinterpret_cast<float4*>(po + q * 4) =
            make_float4(row0[4 * q], row0[4 * q + 1], row0[4 * q + 2], row0[4 * q + 3]);
        *reinterpret_cast<float4*>(po + 64 + q * 4) =
            make_float4(row1[4 * q], row1[4 * q + 1], row1[4 * q + 2], row1[4 * q + 3]);
    }
}

// ---------------------------------------------------------------------------
extern "C" void kernel_launch(void* const* d_in, const int* in_sizes, int n_in,
                              void* d_out, int out_size) {
    const float *X = 0, *cw = 0, *cb = 0, *c1 = 0, *c2 = 0, *c3 = 0;
    for (int i = 0; i < n_in; ++i) {
        const float* pp = (const float*)d_in[i];
        switch (in_sizes[i]) {
            case 8388608: X  = pp; break;
            case 144:     cw = pp; break;
            case 16:      cb = pp; break;
            case 4096:    c1 = pp; break;
            case 16384:   c2 = pp; break;
            case 1024:    c3 = pp; break;
            default: break;
        }
    }

    cudaFuncSetAttribute(wino_gemm, cudaFuncAttributeMaxDynamicSharedMemorySize,
                         GEMM_SMEM);

    wino_weights<<<256, 256>>>(c1, c2, c3, cw, cb);
    wino_input<<<dim3(32, 8, 8), 256>>>(X);
    wino_gemm<<<dim3(32, 2, 16), 256, GEMM_SMEM>>>();
    wino_output<<<1024, 256>>>((float*)d_out);
}

// round 15
// speedup vs baseline: 1.0876x; 1.0876x over previous
#include <cuda_runtime.h>
#include <cuda_fp16.h>
#include <cstdint>

// ============================================================================
// TTConv -> folded dense 256->256 3x3 conv -> Winograd F(2x2,3x3), UNFUSED.
// Round 15: exact round-13 state (3-stage GEMM pipeline, merged weights,
// proven input transform) + wino_output at grid 2048 x 256 thr (4 tiles per
// thread, uint2 loads) to double resident warps at constant traffic.
// ============================================================================

// ---------------- device scratch (no allocations allowed) -------------------
__device__ float  g_beff[256];
__device__ __half g_Usw[2 * 16 * 8 * 128 * 32];     // 2 MB
__device__ __half g_V[16ull * 8192 * 256];          // 64 MB
__device__ __half g_M[16ull * 256 * 8192];          // 64 MB

// ---------------- helpers ---------------------------------------------------
__device__ __forceinline__ uint32_t smem_u32(const void* p) {
    uint32_t a;
    asm("{ .reg .u64 t; cvta.to.shared.u64 t, %1; cvt.u32.u64 %0, t; }"
        : "=r"(a) : "l"(p));
    return a;
}

#define CP16(dst, src) \
    asm volatile("cp.async.ca.shared.global [%0], [%1], 16;" \
                 :: "r"(dst), "l"(src) : "memory")
#define CP_COMMIT() asm volatile("cp.async.commit_group;" ::: "memory")
#define CP_WAIT2()  asm volatile("cp.async.wait_group 2;" ::: "memory")
#define CP_WAIT1()  asm volatile("cp.async.wait_group 1;" ::: "memory")
#define CP_WAIT0()  asm volatile("cp.async.wait_group 0;" ::: "memory")

#define LDSM4(r0, r1, r2, r3, addr) \
    asm volatile("ldmatrix.sync.aligned.m8n8.x4.shared.b16 {%0,%1,%2,%3}, [%4];" \
                 : "=r"(r0), "=r"(r1), "=r"(r2), "=r"(r3) : "r"(addr))

#define MMA16816(c, a0, a1, a2, a3, b0, b1) \
    asm volatile("mma.sync.aligned.m16n8k16.row.col.f32.f16.f16.f32 " \
                 "{%0,%1,%2,%3}, {%4,%5,%6,%7}, {%8,%9}, {%0,%1,%2,%3};" \
                 : "+f"((c)[0]), "+f"((c)[1]), "+f"((c)[2]), "+f"((c)[3]) \
                 : "r"(a0), "r"(a1), "r"(a2), "r"(a3), "r"(b0), "r"(b1))

// ---------------------------------------------------------------------------
// K1 (merged): weight transform + beff.   [proven round-13]
// ---------------------------------------------------------------------------
__global__ void wino_weights(const float* __restrict__ core1,
                             const float* __restrict__ core2,
                             const float* __restrict__ core3,
                             const float* __restrict__ conv_w,
                             const float* __restrict__ conv_b) {
    __shared__ float Psl[1024];
    __shared__ float Gsl[4][144];
    __shared__ float bsl[4][16];
    __shared__ float red[256];

    int o = blockIdx.x, ic = threadIdx.x, tid = threadIdx.x;
    int a = o >> 6, c = (o >> 3) & 7, d = o & 7;

#pragma unroll
    for (int it = 0; it < 4; ++it) {
        int e = tid + it * 256;
        int u = e & 15, k = (e >> 4) & 7, j = (e >> 7) & 7;
        float s = 0.f;
#pragma unroll
        for (int v = 0; v < 16; ++v)
            s += core2[(c * 16 + v) * 128 + u * 8 + j] * core3[d * 128 + v * 8 + k];
        Psl[e] = s;
    }
    for (int e = tid; e < 576; e += 256) {
        int i = e / 144, rem = e - i * 144;
        int tap = rem >> 4, u = rem & 15;
        float s = 0.f;
#pragma unroll
        for (int r = 0; r < 16; ++r)
            s += core1[(a * 16 + u) * 64 + r * 4 + i] * conv_w[r * 9 + tap];
        Gsl[i][rem] = s;
    }
    if (tid < 64) {
        int i = tid >> 4, u = tid & 15;
        float s = 0.f;
#pragma unroll
        for (int r = 0; r < 16; ++r)
            s += core1[(a * 16 + u) * 64 + r * 4 + i] * conv_b[r];
        bsl[i][u] = s;
    }
    __syncthreads();

    int i = ic >> 6, j = (ic >> 3) & 7, k = ic & 7;
    float Pu[16];
#pragma unroll
    for (int u = 0; u < 16; ++u) Pu[u] = Psl[(j * 8 + k) * 16 + u];

    float f[3][3];
#pragma unroll
    for (int tap = 0; tap < 9; ++tap) {
        float s = 0.f;
#pragma unroll
        for (int u = 0; u < 16; ++u) s += Gsl[i][tap * 16 + u] * Pu[u];
        f[tap / 3][tap % 3] = s;
    }
    float t[4][3];
#pragma unroll
    for (int cc = 0; cc < 3; ++cc) {
        t[0][cc] = f[0][cc];
        t[1][cc] = 0.5f * (f[0][cc] + f[1][cc] + f[2][cc]);
        t[2][cc] = 0.5f * (f[0][cc] - f[1][cc] + f[2][cc]);
        t[3][cc] = f[2][cc];
    }
    float u4[4][4];
#pragma unroll
    for (int r = 0; r < 4; ++r) {
        u4[r][0] = t[r][0];
        u4[r][1] = 0.5f * (t[r][0] + t[r][1] + t[r][2]);
        u4[r][2] = 0.5f * (t[r][0] - t[r][1] + t[r][2]);
        u4[r][3] = t[r][2];
    }
    int kk = ic & 31, icb = ic >> 5;
    int o_l = o & 127, mh = o >> 7;
    int swkk = ((((kk >> 3) ^ ((o_l >> 1) & 3)) << 3) | (kk & 7));
#pragma unroll
    for (int p = 0; p < 16; ++p)
        g_Usw[((size_t)((mh * 16 + p) * 8 + icb) * 128 + o_l) * 32 + swkk] =
            __float2half_rn(u4[p >> 2][p & 3]);

    float bp = 0.f;
#pragma unroll
    for (int u = 0; u < 16; ++u) bp += bsl[i][u] * Pu[u];
    red[ic] = bp;
    __syncthreads();
    for (int s = 128; s > 0; s >>= 1) {
        if (ic < s) red[ic] += red[ic + s];
        __syncthreads();
    }
    if (ic == 0) g_beff[o] = red[0];
}

// ---------------------------------------------------------------------------
// K2: input transform -> g_V.   [proven]
// ---------------------------------------------------------------------------
__global__ void wino_input(const float* __restrict__ X) {
    int ty = blockIdx.x, icb = blockIdx.y, b = blockIdx.z;
    int tid = threadIdx.x;
    __shared__ float xs[4][66][33];

    {
        const float* Xb = X + ((size_t)b * 256 + icb * 32) * 4096;
#pragma unroll 4
        for (int it = 0; it < 32; ++it) {
            int e = tid + it * 256;
            int rem = e & 255;
            int y = rem >> 6, x = rem & 63;
            int gy = 2 * ty - 1 + y;
            float v = 0.f;
            if (gy >= 0 && gy < 64) v = Xb[((size_t)it * 64 + gy) * 64 + x];
            xs[y][x + 1][it] = v;
        }
        int icl = tid & 31, y = (tid >> 5) & 3, side = tid >> 7;
        xs[y][side ? 65 : 0][icl] = 0.f;
    }
    __syncthreads();

    int w = tid >> 5, lane = tid & 31;
    int n_row = (b * 32 + ty) * 32;
#pragma unroll
    for (int tt = 0; tt < 4; ++tt) {
        int tx = w * 4 + tt;
        int n = n_row + tx;
        float d0[4], d1[4], d2[4], d3[4];
#pragma unroll
        for (int cc = 0; cc < 4; ++cc) {
            d0[cc] = xs[0][2 * tx + cc][lane];
            d1[cc] = xs[1][2 * tx + cc][lane];
            d2[cc] = xs[2][2 * tx + cc][lane];
            d3[cc] = xs[3][2 * tx + cc][lane];
        }
        float w0[4], w1[4], w2[4], w3[4];
#pragma unroll
        for (int cc = 0; cc < 4; ++cc) {
            w0[cc] = d0[cc] - d2[cc];
            w1[cc] = d1[cc] + d2[cc];
            w2[cc] = d2[cc] - d1[cc];
            w3[cc] = d1[cc] - d3[cc];
        }
        float v[4][4];
#pragma unroll
        for (int r = 0; r < 4; ++r) {
            const float* wr = (r == 0) ? w0 : (r == 1) ? w1 : (r == 2) ? w2 : w3;
            v[r][0] = wr[0] - wr[2];
            v[r][1] = wr[1] + wr[2];
            v[r][2] = wr[2] - wr[1];
            v[r][3] = wr[1] - wr[3];
        }
        __half* Vb = g_V + (size_t)n * 256 + icb * 32 + lane;
#pragma unroll
        for (int p = 0; p < 16; ++p)
            Vb[(size_t)p * 8192 * 256] = __float2half_rn(v[p >> 2][p & 3]);
    }
}

// ---------------------------------------------------------------------------
// K3: batched GEMM, 1024-CTA grid, 3-stage cp.async pipeline.  [round-13]
// ---------------------------------------------------------------------------
static constexpr int BA   = 8192;
static constexpr int BB   = 20480;
static constexpr int BSTG = BA + BB;            // 28672
static constexpr int GEMM_SMEM = 3 * BSTG;      // 86016

__global__ __launch_bounds__(256, 1)
void wino_gemm() {
    extern __shared__ char smc[];
    const uint32_t sb = smem_u32(smc);
    const int tid  = threadIdx.x;
    const int warp = tid >> 5, lane = tid & 31;
    const int warpM = warp >> 2;
    const int warpN = warp & 3;
    const int n0 = blockIdx.x * 256;
    const int mh = blockIdx.y;
    const int p  = blockIdx.z;

    const int r15 = lane & 15, hi = lane >> 4;
    const int sw  = (r15 >> 1) & 3;
    const uint32_t l0 = (uint32_t)(r15 * 64 + ((hi ^ sw) << 4));
    const uint32_t l1 = (uint32_t)(r15 * 64 + (((2 + hi) ^ sw) << 4));
    const uint32_t xLane = (uint32_t)((((lane >> 4) & 1) * 8 + (lane & 7)) * 80 +
                                      ((lane >> 3) & 1) * 16);

    auto stage = [&](int kc) {
        const int buf = kc % 3;
        uint32_t dst = sb + buf * BSTG;
        const char* srcA = (const char*)(g_Usw +
            (size_t)((mh * 16 + p) * 8 + kc) * 4096);
        CP16(dst + tid * 16, srcA + tid * 16);
        CP16(dst + (tid + 256) * 16, srcA + (tid + 256) * 16);
        const char* srcB = (const char*)(g_V + ((size_t)p * 8192 + n0) * 256) + kc * 64;
        uint32_t dstB = dst + BA;
#pragma unroll
        for (int i = 0; i < 4; ++i) {
            int e = tid + i * 256;
            int row = e >> 2, cc = e & 3;
            CP16(dstB + row * 80 + cc * 16, srcB + (size_t)row * 512 + cc * 16);
        }
    };

    float acc[4][8][4];
#pragma unroll
    for (int m = 0; m < 4; ++m)
#pragma unroll
        for (int n = 0; n < 8; ++n)
#pragma unroll
            for (int q = 0; q < 4; ++q) acc[m][n][q] = 0.f;

    stage(0); CP_COMMIT();
    stage(1); CP_COMMIT();
    stage(2); CP_COMMIT();

    for (int kc = 0; kc < 8; ++kc) {
        const int buf = kc % 3;
        if (kc < 6) CP_WAIT2();
        else if (kc == 6) CP_WAIT1();
        else CP_WAIT0();
        __syncthreads();
        const uint32_t aB = sb + buf * BSTG;
        const uint32_t bB = aB + BA;
        const uint32_t xT = bB + (uint32_t)(warpN * 64 * 80) + xLane;

#pragma unroll
        for (int ks = 0; ks < 2; ++ks) {
            const uint32_t lks = ks ? l1 : l0;
            uint32_t af[4][4];
#pragma unroll
            for (int mt = 0; mt < 4; ++mt)
                LDSM4(af[mt][0], af[mt][1], af[mt][2], af[mt][3],
                      aB + (uint32_t)((warpM * 64 + mt * 16) * 64) + lks);
#pragma unroll
            for (int q = 0; q < 4; ++q) {
                uint32_t b0, b1, b2, b3;
                LDSM4(b0, b1, b2, b3, xT + q * (16 * 80) + ks * 32);
#pragma unroll
                for (int mt = 0; mt < 4; ++mt) {
                    MMA16816(acc[mt][2 * q],     af[mt][0], af[mt][1],
                             af[mt][2], af[mt][3], b0, b1);
                    MMA16816(acc[mt][2 * q + 1], af[mt][0], af[mt][1],
                             af[mt][2], af[mt][3], b2, b3);
                }
            }
        }
        __syncthreads();
        if (kc + 3 < 8) { stage(kc + 3); CP_COMMIT(); }
    }

#pragma unroll
    for (int mt = 0; mt < 4; ++mt) {
        int oA = mh * 128 + warpM * 64 + mt * 16 + (lane >> 2);
        __half* baseLo = g_M + ((size_t)p * 256 + oA) * 8192 + n0 +
                         warpN * 64 + (lane & 3) * 2;
        __half* baseHi = baseLo + (size_t)8 * 8192;
#pragma unroll
        for (int nt = 0; nt < 8; ++nt) {
            __half2 vLo = __floats2half2_rn(acc[mt][nt][0], acc[mt][nt][1]);
            __half2 vHi = __floats2half2_rn(acc[mt][nt][2], acc[mt][nt][3]);
            *reinterpret_cast<__half2*>(baseLo + nt * 8) = vLo;
            *reinterpret_cast<__half2*>(baseHi + nt * 8) = vHi;
        }
    }
}

// ---------------------------------------------------------------------------
// K4: output transform. grid 2048 (b*256+o) x 256 thr, 4 tiles/thread.
//   2x resident warps vs round-13 at identical traffic (uint2 loads).
// ---------------------------------------------------------------------------
__global__ void wino_output(float* __restrict__ out) {
    int blk = blockIdx.x;
    int b = blk >> 8, o = blk & 255;
    int tid = threadIdx.x;           // 256 threads, 4 tiles each
    int nbase = b * 1024 + tid * 4;

    uint2 mv[16];
#pragma unroll
    for (int p = 0; p < 16; ++p)
        mv[p] = *reinterpret_cast<const uint2*>(
            g_M + ((size_t)p * 256 + o) * 8192 + nbase);

    float bv = g_beff[o];
    float row0[8], row1[8];
#pragma unroll
    for (int t = 0; t < 4; ++t) {
        float m[16];
#pragma unroll
        for (int p = 0; p < 16; ++p) {
            unsigned wbits = (t < 2) ? mv[p].x : mv[p].y;
            __half2 h = *reinterpret_cast<__half2*>(&wbits);
            m[p] = (t & 1) ? __high2float(h) : __low2float(h);
        }
        float z0[4], z1[4];
#pragma unroll
        for (int cc = 0; cc < 4; ++cc) {
            z0[cc] = m[cc] + m[4 + cc] + m[8 + cc];
            z1[cc] = m[4 + cc] - m[8 + cc] - m[12 + cc];
        }
        row0[2 * t]     = z0[0] + z0[1] + z0[2] + bv;
        row0[2 * t + 1] = z0[1] - z0[2] - z0[3] + bv;
        row1[2 * t]     = z1[0] + z1[1] + z1[2] + bv;
        row1[2 * t + 1] = z1[1] - z1[2] - z1[3] + bv;
    }

    int ty = (nbase >> 5) & 31;
    int tx0 = nbase & 31;
    float* po = out + (((size_t)b * 256 + o) * 64 + 2 * ty) * 64 + 2 * tx0;
#pragma unroll
    for (int q = 0; q < 2; ++q) {
        *reinterpret_cast<float4*>(po + q * 4) =
            make_float4(row0[4 * q], row0[4 * q + 1], row0[4 * q + 2], row0[4 * q + 3]);
        *reinterpret_cast<float4*>(po + 64 + q * 4) =
            make_float4(row1[4 * q], row1[4 * q + 1], row1[4 * q + 2], row1[4 * q + 3]);
    }
}

// ---------------------------------------------------------------------------
extern "C" void kernel_launch(void* const* d_in, const int* in_sizes, int n_in,
                              void* d_out, int out_size) {
    const float *X = 0, *cw = 0, *cb = 0, *c1 = 0, *c2 = 0, *c3 = 0;
    for (int i = 0; i < n_in; ++i) {
        const float* pp = (const float*)d_in[i];
        switch (in_sizes[i]) {
            case 8388608: X  = pp; break;
            case 144:     cw = pp; break;
            case 16:      cb = pp; break;
            case 4096:    c1 = pp; break;
            case 16384:   c2 = pp; break;
            case 1024:    c3 = pp; break;
            default: break;
        }
    }

    cudaFuncSetAttribute(wino_gemm, cudaFuncAttributeMaxDynamicSharedMemorySize,
                         GEMM_SMEM);

    wino_weights<<<256, 256>>>(c1, c2, c3, cw, cb);
    wino_input<<<dim3(32, 8, 8), 256>>>(X);
    wino_gemm<<<dim3(32, 2, 16), 256, GEMM_SMEM>>>();
    wino_output<<<2048, 256>>>((float*)d_out);
}

// round 16
// speedup vs baseline: 1.1067x; 1.0175x over previous
#include <cuda_runtime.h>
#include <cuda_fp16.h>
#include <cstdint>

// ============================================================================
// TTConv -> folded dense 256->256 3x3 conv -> Winograd F(2x2,3x3), UNFUSED.
// Round 16: GEMM CTA retiled M128xN256 -> M256xN128 so each V block is read
// by exactly ONE CTA (V DRAM reads halved). Warp tile / inner loop / grid
// wave structure unchanged. A layout in g_Usw: [p][kc][o 256][32].
// ============================================================================

// ---------------- device scratch (no allocations allowed) -------------------
__device__ float  g_beff[256];
__device__ __half g_Usw[16 * 8 * 256 * 32];         // 2 MB, [p][kc][o][32]
__device__ __half g_V[16ull * 8192 * 256];          // 64 MB
__device__ __half g_M[16ull * 256 * 8192];          // 64 MB

// ---------------- helpers ---------------------------------------------------
__device__ __forceinline__ uint32_t smem_u32(const void* p) {
    uint32_t a;
    asm("{ .reg .u64 t; cvta.to.shared.u64 t, %1; cvt.u32.u64 %0, t; }"
        : "=r"(a) : "l"(p));
    return a;
}

#define CP16(dst, src) \
    asm volatile("cp.async.ca.shared.global [%0], [%1], 16;" \
                 :: "r"(dst), "l"(src) : "memory")
#define CP_COMMIT() asm volatile("cp.async.commit_group;" ::: "memory")
#define CP_WAIT2()  asm volatile("cp.async.wait_group 2;" ::: "memory")
#define CP_WAIT1()  asm volatile("cp.async.wait_group 1;" ::: "memory")
#define CP_WAIT0()  asm volatile("cp.async.wait_group 0;" ::: "memory")

#define LDSM4(r0, r1, r2, r3, addr) \
    asm volatile("ldmatrix.sync.aligned.m8n8.x4.shared.b16 {%0,%1,%2,%3}, [%4];" \
                 : "=r"(r0), "=r"(r1), "=r"(r2), "=r"(r3) : "r"(addr))

#define MMA16816(c, a0, a1, a2, a3, b0, b1) \
    asm volatile("mma.sync.aligned.m16n8k16.row.col.f32.f16.f16.f32 " \
                 "{%0,%1,%2,%3}, {%4,%5,%6,%7}, {%8,%9}, {%0,%1,%2,%3};" \
                 : "+f"((c)[0]), "+f"((c)[1]), "+f"((c)[2]), "+f"((c)[3]) \
                 : "r"(a0), "r"(a1), "r"(a2), "r"(a3), "r"(b0), "r"(b1))

// ---------------------------------------------------------------------------
// K1 (merged): weight transform + beff. A layout: [(p*8+kc)*256 + o][32].
// ---------------------------------------------------------------------------
__global__ void wino_weights(const float* __restrict__ core1,
                             const float* __restrict__ core2,
                             const float* __restrict__ core3,
                             const float* __restrict__ conv_w,
                             const float* __restrict__ conv_b) {
    __shared__ float Psl[1024];
    __shared__ float Gsl[4][144];
    __shared__ float bsl[4][16];
    __shared__ float red[256];

    int o = blockIdx.x, ic = threadIdx.x, tid = threadIdx.x;
    int a = o >> 6, c = (o >> 3) & 7, d = o & 7;

#pragma unroll
    for (int it = 0; it < 4; ++it) {
        int e = tid + it * 256;
        int u = e & 15, k = (e >> 4) & 7, j = (e >> 7) & 7;
        float s = 0.f;
#pragma unroll
        for (int v = 0; v < 16; ++v)
            s += core2[(c * 16 + v) * 128 + u * 8 + j] * core3[d * 128 + v * 8 + k];
        Psl[e] = s;
    }
    for (int e = tid; e < 576; e += 256) {
        int i = e / 144, rem = e - i * 144;
        int tap = rem >> 4, u = rem & 15;
        float s = 0.f;
#pragma unroll
        for (int r = 0; r < 16; ++r)
            s += core1[(a * 16 + u) * 64 + r * 4 + i] * conv_w[r * 9 + tap];
        Gsl[i][rem] = s;
    }
    if (tid < 64) {
        int i = tid >> 4, u = tid & 15;
        float s = 0.f;
#pragma unroll
        for (int r = 0; r < 16; ++r)
            s += core1[(a * 16 + u) * 64 + r * 4 + i] * conv_b[r];
        bsl[i][u] = s;
    }
    __syncthreads();

    int i = ic >> 6, j = (ic >> 3) & 7, k = ic & 7;
    float Pu[16];
#pragma unroll
    for (int u = 0; u < 16; ++u) Pu[u] = Psl[(j * 8 + k) * 16 + u];

    float f[3][3];
#pragma unroll
    for (int tap = 0; tap < 9; ++tap) {
        float s = 0.f;
#pragma unroll
        for (int u = 0; u < 16; ++u) s += Gsl[i][tap * 16 + u] * Pu[u];
        f[tap / 3][tap % 3] = s;
    }
    float t[4][3];
#pragma unroll
    for (int cc = 0; cc < 3; ++cc) {
        t[0][cc] = f[0][cc];
        t[1][cc] = 0.5f * (f[0][cc] + f[1][cc] + f[2][cc]);
        t[2][cc] = 0.5f * (f[0][cc] - f[1][cc] + f[2][cc]);
        t[3][cc] = f[2][cc];
    }
    float u4[4][4];
#pragma unroll
    for (int r = 0; r < 4; ++r) {
        u4[r][0] = t[r][0];
        u4[r][1] = 0.5f * (t[r][0] + t[r][1] + t[r][2]);
        u4[r][2] = 0.5f * (t[r][0] - t[r][1] + t[r][2]);
        u4[r][3] = t[r][2];
    }
    int kk = ic & 31, icb = ic >> 5;
    int swkk = ((((kk >> 3) ^ ((o >> 1) & 3)) << 3) | (kk & 7));
#pragma unroll
    for (int p = 0; p < 16; ++p)
        g_Usw[((size_t)((p * 8 + icb) * 256 + o)) * 32 + swkk] =
            __float2half_rn(u4[p >> 2][p & 3]);

    float bp = 0.f;
#pragma unroll
    for (int u = 0; u < 16; ++u) bp += bsl[i][u] * Pu[u];
    red[ic] = bp;
    __syncthreads();
    for (int s = 128; s > 0; s >>= 1) {
        if (ic < s) red[ic] += red[ic + s];
        __syncthreads();
    }
    if (ic == 0) g_beff[o] = red[0];
}

// ---------------------------------------------------------------------------
// K2: input transform -> g_V.   [proven]
// ---------------------------------------------------------------------------
__global__ void wino_input(const float* __restrict__ X) {
    int ty = blockIdx.x, icb = blockIdx.y, b = blockIdx.z;
    int tid = threadIdx.x;
    __shared__ float xs[4][66][33];

    {
        const float* Xb = X + ((size_t)b * 256 + icb * 32) * 4096;
#pragma unroll 4
        for (int it = 0; it < 32; ++it) {
            int e = tid + it * 256;
            int rem = e & 255;
            int y = rem >> 6, x = rem & 63;
            int gy = 2 * ty - 1 + y;
            float v = 0.f;
            if (gy >= 0 && gy < 64) v = Xb[((size_t)it * 64 + gy) * 64 + x];
            xs[y][x + 1][it] = v;
        }
        int icl = tid & 31, y = (tid >> 5) & 3, side = tid >> 7;
        xs[y][side ? 65 : 0][icl] = 0.f;
    }
    __syncthreads();

    int w = tid >> 5, lane = tid & 31;
    int n_row = (b * 32 + ty) * 32;
#pragma unroll
    for (int tt = 0; tt < 4; ++tt) {
        int tx = w * 4 + tt;
        int n = n_row + tx;
        float d0[4], d1[4], d2[4], d3[4];
#pragma unroll
        for (int cc = 0; cc < 4; ++cc) {
            d0[cc] = xs[0][2 * tx + cc][lane];
            d1[cc] = xs[1][2 * tx + cc][lane];
            d2[cc] = xs[2][2 * tx + cc][lane];
            d3[cc] = xs[3][2 * tx + cc][lane];
        }
        float w0[4], w1[4], w2[4], w3[4];
#pragma unroll
        for (int cc = 0; cc < 4; ++cc) {
            w0[cc] = d0[cc] - d2[cc];
            w1[cc] = d1[cc] + d2[cc];
            w2[cc] = d2[cc] - d1[cc];
            w3[cc] = d1[cc] - d3[cc];
        }
        float v[4][4];
#pragma unroll
        for (int r = 0; r < 4; ++r) {
            const float* wr = (r == 0) ? w0 : (r == 1) ? w1 : (r == 2) ? w2 : w3;
            v[r][0] = wr[0] - wr[2];
            v[r][1] = wr[1] + wr[2];
            v[r][2] = wr[2] - wr[1];
            v[r][3] = wr[1] - wr[3];
        }
        __half* Vb = g_V + (size_t)n * 256 + icb * 32 + lane;
#pragma unroll
        for (int p = 0; p < 16; ++p)
            Vb[(size_t)p * 8192 * 256] = __float2half_rn(v[p >> 2][p & 3]);
    }
}

// ---------------------------------------------------------------------------
// K3: batched GEMM, CTA = M256 x N128, grid (64 ngroups, 16 p) = 1024 CTAs,
//     3-stage cp.async pipeline. Warp tile M64 x N64 (8 warps = 4M x 2N).
// ---------------------------------------------------------------------------
static constexpr int BA   = 16384;              // A chunk: 256 x 64B
static constexpr int BB   = 10240;              // B chunk: 128 x 80B
static constexpr int BSTG = BA + BB;            // 26624
static constexpr int GEMM_SMEM = 3 * BSTG;      // 79872

__global__ __launch_bounds__(256, 1)
void wino_gemm() {
    extern __shared__ char smc[];
    const uint32_t sb = smem_u32(smc);
    const int tid  = threadIdx.x;
    const int warp = tid >> 5, lane = tid & 31;
    const int warpM = warp >> 1;          // 0..3 -> o block of 64
    const int warpN = warp & 1;           // 0..1 -> n block of 64
    const int n0 = blockIdx.x * 128;
    const int p  = blockIdx.y;

    const int r15 = lane & 15, hi = lane >> 4;
    const int sw  = (r15 >> 1) & 3;
    const uint32_t l0 = (uint32_t)(r15 * 64 + ((hi ^ sw) << 4));
    const uint32_t l1 = (uint32_t)(r15 * 64 + (((2 + hi) ^ sw) << 4));
    const uint32_t xLane = (uint32_t)((((lane >> 4) & 1) * 8 + (lane & 7)) * 80 +
                                      ((lane >> 3) & 1) * 16);

    auto stage = [&](int kc) {
        const int buf = kc % 3;
        uint32_t dst = sb + buf * BSTG;
        // A: 256 rows x 64B = 1024 x 16B
        const char* srcA = (const char*)(g_Usw + (size_t)(p * 8 + kc) * 8192);
#pragma unroll
        for (int i = 0; i < 4; ++i) {
            int e = tid + i * 256;
            CP16(dst + e * 16, srcA + e * 16);
        }
        // B: 128 rows x 64B -> 80B padded = 512 x 16B
        const char* srcB = (const char*)(g_V + ((size_t)p * 8192 + n0) * 256) + kc * 64;
        uint32_t dstB = dst + BA;
#pragma unroll
        for (int i = 0; i < 2; ++i) {
            int e = tid + i * 256;
            int row = e >> 2, cc = e & 3;
            CP16(dstB + row * 80 + cc * 16, srcB + (size_t)row * 512 + cc * 16);
        }
    };

    float acc[4][8][4];
#pragma unroll
    for (int m = 0; m < 4; ++m)
#pragma unroll
        for (int n = 0; n < 8; ++n)
#pragma unroll
            for (int q = 0; q < 4; ++q) acc[m][n][q] = 0.f;

    stage(0); CP_COMMIT();
    stage(1); CP_COMMIT();
    stage(2); CP_COMMIT();

    for (int kc = 0; kc < 8; ++kc) {
        const int buf = kc % 3;
        if (kc < 6) CP_WAIT2();
        else if (kc == 6) CP_WAIT1();
        else CP_WAIT0();
        __syncthreads();
        const uint32_t aB = sb + buf * BSTG;
        const uint32_t bB = aB + BA;
        const uint32_t xT = bB + (uint32_t)(warpN * 64 * 80) + xLane;

#pragma unroll
        for (int ks = 0; ks < 2; ++ks) {
            const uint32_t lks = ks ? l1 : l0;
            uint32_t af[4][4];
#pragma unroll
            for (int mt = 0; mt < 4; ++mt)
                LDSM4(af[mt][0], af[mt][1], af[mt][2], af[mt][3],
                      aB + (uint32_t)((warpM * 64 + mt * 16) * 64) + lks);
#pragma unroll
            for (int q = 0; q < 4; ++q) {
                uint32_t b0, b1, b2, b3;
                LDSM4(b0, b1, b2, b3, xT + q * (16 * 80) + ks * 32);
#pragma unroll
                for (int mt = 0; mt < 4; ++mt) {
                    MMA16816(acc[mt][2 * q],     af[mt][0], af[mt][1],
                             af[mt][2], af[mt][3], b0, b1);
                    MMA16816(acc[mt][2 * q + 1], af[mt][0], af[mt][1],
                             af[mt][2], af[mt][3], b2, b3);
                }
            }
        }
        __syncthreads();
        if (kc + 3 < 8) { stage(kc + 3); CP_COMMIT(); }
    }

#pragma unroll
    for (int mt = 0; mt < 4; ++mt) {
        int oA = warpM * 64 + mt * 16 + (lane >> 2);
        __half* baseLo = g_M + ((size_t)p * 256 + oA) * 8192 + n0 +
                         warpN * 64 + (lane & 3) * 2;
        __half* baseHi = baseLo + (size_t)8 * 8192;
#pragma unroll
        for (int nt = 0; nt < 8; ++nt) {
            __half2 vLo = __floats2half2_rn(acc[mt][nt][0], acc[mt][nt][1]);
            __half2 vHi = __floats2half2_rn(acc[mt][nt][2], acc[mt][nt][3]);
            *reinterpret_cast<__half2*>(baseLo + nt * 8) = vLo;
            *reinterpret_cast<__half2*>(baseHi + nt * 8) = vHi;
        }
    }
}

// ---------------------------------------------------------------------------
// K4: output transform. grid 2048 x 256 thr, 4 tiles/thread.  [round-15]
// ---------------------------------------------------------------------------
__global__ void wino_output(float* __restrict__ out) {
    int blk = blockIdx.x;
    int b = blk >> 8, o = blk & 255;
    int tid = threadIdx.x;
    int nbase = b * 1024 + tid * 4;

    uint2 mv[16];
#pragma unroll
    for (int p = 0; p < 16; ++p)
        mv[p] = *reinterpret_cast<const uint2*>(
            g_M + ((size_t)p * 256 + o) * 8192 + nbase);

    float bv = g_beff[o];
    float row0[8], row1[8];
#pragma unroll
    for (int t = 0; t < 4; ++t) {
        float m[16];
#pragma unroll
        for (int p = 0; p < 16; ++p) {
            unsigned wbits = (t < 2) ? mv[p].x : mv[p].y;
            __half2 h = *reinterpret_cast<__half2*>(&wbits);
            m[p] = (t & 1) ? __high2float(h) : __low2float(h);
        }
        float z0[4], z1[4];
#pragma unroll
        for (int cc = 0; cc < 4; ++cc) {
            z0[cc] = m[cc] + m[4 + cc] + m[8 + cc];
            z1[cc] = m[4 + cc] - m[8 + cc] - m[12 + cc];
        }
        row0[2 * t]     = z0[0] + z0[1] + z0[2] + bv;
        row0[2 * t + 1] = z0[1] - z0[2] - z0[3] + bv;
        row1[2 * t]     = z1[0] + z1[1] + z1[2] + bv;
        row1[2 * t + 1] = z1[1] - z1[2] - z1[3] + bv;
    }

    int ty = (nbase >> 5) & 31;
    int tx0 = nbase & 31;
    float* po = out + (((size_t)b * 256 + o) * 64 + 2 * ty) * 64 + 2 * tx0;
#pragma unroll
    for (int q = 0; q < 2; ++q) {
        *reinterpret_cast<float4*>(po + q * 4) =
            make_float4(row0[4 * q], row0[4 * q + 1], row0[4 * q + 2], row0[4 * q + 3]);
        *reinterpret_cast<float4*>(po + 64 + q * 4) =
            make_float4(row1[4 * q], row1[4 * q + 1], row1[4 * q + 2], row1[4 * q + 3]);
    }
}

// ---------------------------------------------------------------------------
extern "C" void kernel_launch(void* const* d_in, const int* in_sizes, int n_in,
                              void* d_out, int out_size) {
    const float *X = 0, *cw = 0, *cb = 0, *c1 = 0, *c2 = 0, *c3 = 0;
    for (int i = 0; i < n_in; ++i) {
        const float* pp = (const float*)d_in[i];
        switch (in_sizes[i]) {
            case 8388608: X  = pp; break;
            case 144:     cw = pp; break;
            case 16:      cb = pp; break;
            case 4096:    c1 = pp; break;
            case 16384:   c2 = pp; break;
            case 1024:    c3 = pp; break;
            default: break;
        }
    }

    cudaFuncSetAttribute(wino_gemm, cudaFuncAttributeMaxDynamicSharedMemorySize,
                         GEMM_SMEM);

    wino_weights<<<256, 256>>>(c1, c2, c3, cw, cb);
    wino_input<<<dim3(32, 8, 8), 256>>>(X);
    wino_gemm<<<dim3(64, 16), 256, GEMM_SMEM>>>();
    wino_output<<<2048, 256>>>((float*)d_out);
}